// round 12
// baseline (speedup 1.0000x reference)
#include <cuda_runtime.h>
#include <math.h>

#define N    768
#define CN   384
#define CZ   128
#define CC   16
#define H    12
#define PQ   4
#define PV   8
#define NN   (N*N)                 // 589824
#define HC   (H*CC)                // 192
#define KV_COLS (2*HC)             // 384
#define QP_COLS (H*PQ*3)           // 144
#define KVP_COLS (H*12*3)          // 432
#define CAT_DIM (H*(CZ+CC+PV*4))   // 2112
#define INFV 100000.0f
#define EPSV 1e-8f

// ---- k_zfused smem layout (floats) ----
#define ZOFF_SZ    0                      // 64*132 = 8448 (aliased as rbuf in epilogue)
#define ZOFF_WBT   8448                   // 12*128 = 1536
#define ZOFF_QKT   9984                   // 12*64  = 768
#define ZOFF_ESH   10752                  // 64*12 ull = 1536 floats (e pre-duplicated)
#define ZOFF_RBIAS 12288                  // 4*12*64 = 3072
#define ZOFF_S     15360                  // 12
#define ZOFF_BB    15372                  // 12
#define ZF_SMEM_FLOATS 15392
#define ZF_SMEM_BYTES (ZF_SMEM_FLOATS*4)  // 61568

// ---------------- scratch ----------------
__device__ float g_qlin  [N*HC];
__device__ float g_kvlin [N*KV_COLS];
__device__ float g_qplin [N*QP_COLS];
__device__ float g_kvplin[N*KVP_COLS];
__device__ float g_qpts  [N*H*PQ*3];
__device__ float g_kpts  [N*H*PQ*3];
__device__ float g_vpts  [N*H*PV*3];
__device__ float g_logits[H*NN];        // qk+pt+mask terms, then UNNORMALIZED exp(a)
__device__ float g_sinv  [H*N];         // 1/rowsum per (h, i)
__device__ float g_optg  [N*H*PV*3];
__device__ float g_cat   [N*CAT_DIM];

// ---------------- f32x2 packed helpers ----------------
__device__ __forceinline__ void fma2(unsigned long long& acc, unsigned long long a, unsigned long long b) {
    asm("fma.rn.f32x2 %0, %1, %2, %0;" : "+l"(acc) : "l"(a), "l"(b));
}
__device__ __forceinline__ unsigned long long pk2(float a, float b) {
    unsigned long long r; asm("mov.b64 %0, {%1,%2};" : "=l"(r) : "f"(a), "f"(b)); return r;
}
__device__ __forceinline__ float hsum2(unsigned long long v) {
    float x, y; asm("mov.b64 {%0,%1}, %2;" : "=f"(x), "=f"(y) : "l"(v)); return x + y;
}
__device__ __forceinline__ void unpk2(unsigned long long v, float& x, float& y) {
    asm("mov.b64 {%0,%1}, %2;" : "=f"(x), "=f"(y) : "l"(v));
}

// ---------------- tiled GEMM body: out = A@W + bias ----------------
__device__ __forceinline__ void gemm_tile(const float* __restrict__ A, const float* __restrict__ W,
                                          const float* __restrict__ bias, float* __restrict__ out,
                                          int K, int Nc, int row0, int col0) {
    __shared__ __align__(16) float As[32][33];
    __shared__ __align__(16) float Ws[32][64];
    int t = threadIdx.x;
    int tx = t & 15, ty = t >> 4;
    int lm = t >> 3;
    int lk4 = t & 7;
    float acc[2][4] = {};
    for (int k0 = 0; k0 < K; k0 += 32) {
        float4 a4 = *reinterpret_cast<const float4*>(&A[(long)(row0 + lm) * K + k0 + lk4 * 4]);
        As[lk4 * 4 + 0][lm] = a4.x;
        As[lk4 * 4 + 1][lm] = a4.y;
        As[lk4 * 4 + 2][lm] = a4.z;
        As[lk4 * 4 + 3][lm] = a4.w;
        #pragma unroll
        for (int r = 0; r < 2; r++) {
            int li = t + 256 * r;
            int kk = li >> 4, c4 = li & 15;
            int col = col0 + c4 * 4;
            float4 w4 = make_float4(0.f, 0.f, 0.f, 0.f);
            if (col < Nc)
                w4 = *reinterpret_cast<const float4*>(&W[(long)(k0 + kk) * Nc + col]);
            *reinterpret_cast<float4*>(&Ws[kk][c4 * 4]) = w4;
        }
        __syncthreads();
        #pragma unroll
        for (int kk = 0; kk < 32; kk++) {
            float a0 = As[kk][ty * 2 + 0];
            float a1 = As[kk][ty * 2 + 1];
            float4 w = *reinterpret_cast<const float4*>(&Ws[kk][tx * 4]);
            acc[0][0] += a0 * w.x; acc[0][1] += a0 * w.y; acc[0][2] += a0 * w.z; acc[0][3] += a0 * w.w;
            acc[1][0] += a1 * w.x; acc[1][1] += a1 * w.y; acc[1][2] += a1 * w.z; acc[1][3] += a1 * w.w;
        }
        __syncthreads();
    }
    int col = col0 + tx * 4;
    if (col < Nc) {
        float4 b4 = *reinterpret_cast<const float4*>(&bias[col]);
        #pragma unroll
        for (int r = 0; r < 2; r++) {
            int row = row0 + ty * 2 + r;
            float4 o;
            o.x = acc[r][0] + b4.x; o.y = acc[r][1] + b4.y;
            o.z = acc[r][2] + b4.z; o.w = acc[r][3] + b4.w;
            *reinterpret_cast<float4*>(&out[(long)row * Nc + col]) = o;
        }
    }
}

__global__ void k_proj(const float* __restrict__ s,
                       const float* __restrict__ wq,  const float* __restrict__ bq,
                       const float* __restrict__ wkv, const float* __restrict__ bkv,
                       const float* __restrict__ wqp, const float* __restrict__ bqp,
                       const float* __restrict__ wkvp,const float* __restrict__ bkvp) {
    int bx = blockIdx.x;
    const float* W; const float* b; float* out; int Nc; int ct;
    if (bx < 3)       { W = wq;   b = bq;   out = g_qlin;   Nc = HC;       ct = bx; }
    else if (bx < 9)  { W = wkv;  b = bkv;  out = g_kvlin;  Nc = KV_COLS;  ct = bx - 3; }
    else if (bx < 12) { W = wqp;  b = bqp;  out = g_qplin;  Nc = QP_COLS;  ct = bx - 9; }
    else              { W = wkvp; b = bkvp; out = g_kvplin; Nc = KVP_COLS; ct = bx - 12; }
    gemm_tile(s, W, b, out, CN, Nc, blockIdx.y * 32, ct * 64);
}

__global__ void k_outgemm(const float* __restrict__ W, const float* __restrict__ bias,
                          float* __restrict__ out) {
    gemm_tile(g_cat, W, bias, out, CAT_DIM, CN, blockIdx.y * 32, blockIdx.x * 64);
}

// ---------------- point construction ----------------
__global__ void k_points_all(const float* __restrict__ rot, const float* __restrict__ trans) {
    int idx = blockIdx.x * 256 + threadIdx.x;
    if (idx >= N * 192) return;
    int i = idx / 192, p = idx % 192;
    float l0, l1, l2;
    if (p < 48) {
        const float* lin = g_qplin + i * QP_COLS;
        l0 = lin[p]; l1 = lin[48 + p]; l2 = lin[96 + p];
    } else {
        const float* lin = g_kvplin + i * KVP_COLS;
        int pp = p - 48;
        l0 = lin[pp]; l1 = lin[144 + pp]; l2 = lin[288 + pp];
    }
    const float* R = rot + i * 9;
    float o[3];
    #pragma unroll
    for (int d = 0; d < 3; d++)
        o[d] = R[d * 3 + 0] * l0 + R[d * 3 + 1] * l1 + R[d * 3 + 2] * l2 + trans[i * 3 + d];
    if (p < 48) {
        int h = p / PQ, tt = p % PQ;
        #pragma unroll
        for (int d = 0; d < 3; d++) g_qpts[i * 144 + h * 12 + tt * 3 + d] = o[d];
    } else {
        int pp = p - 48;
        int h = pp / 12, tt = pp % 12;
        if (tt < PQ) {
            #pragma unroll
            for (int d = 0; d < 3; d++) g_kpts[i * 144 + h * 12 + tt * 3 + d] = o[d];
        } else {
            #pragma unroll
            for (int d = 0; d < 3; d++) g_vpts[i * 288 + h * 24 + (tt - PQ) * 3 + d] = o[d];
        }
    }
}

// ---------------- qk + pt_att + mask terms (pure WRITE into g_logits) ----------------
__global__ void k_qk(const float* __restrict__ mask, const float* __restrict__ hwts) {
    __shared__ float qs[32][17], ks[32][17];
    __shared__ float qps[32][13], kps[32][13];
    int h = blockIdx.z;
    int i0 = blockIdx.y * 32, j0 = blockIdx.x * 32;
    int tx = threadIdx.x, ty = threadIdx.y;
    int tid = ty * 16 + tx;
    for (int r = 0; r < 2; r++) {
        int idx = tid + 256 * r;
        int ii = idx >> 4, c = idx & 15;
        qs[ii][c] = g_qlin[(i0 + ii) * HC + h * 16 + c];
        ks[ii][c] = g_kvlin[(j0 + ii) * KV_COLS + h * 32 + c];
        if (idx < 384) {
            int i2 = idx / 12, d = idx % 12;
            qps[i2][d] = g_qpts[(i0 + i2) * 144 + h * 12 + d];
            kps[i2][d] = g_kpts[(j0 + i2) * 144 + h * 12 + d];
        }
    }
    __syncthreads();
    float w = hwts[h];
    float hw = logf(1.0f + expf(w)) * 0.13608276348795434f; // softplus * sqrt(1/54)
    const float QK_SCALE = 0.14433756729740643f;            // sqrt(1/48)
    float dot[2][2] = {};
    float pt[2][2] = {};
    #pragma unroll
    for (int c = 0; c < 16; c++) {
        float a0 = qs[ty * 2][c], a1 = qs[ty * 2 + 1][c];
        float b0 = ks[tx * 2][c], b1 = ks[tx * 2 + 1][c];
        dot[0][0] += a0 * b0; dot[0][1] += a0 * b1;
        dot[1][0] += a1 * b0; dot[1][1] += a1 * b1;
    }
    #pragma unroll
    for (int d = 0; d < 12; d++) {
        float a0 = qps[ty * 2][d], a1 = qps[ty * 2 + 1][d];
        float b0 = kps[tx * 2][d], b1 = kps[tx * 2 + 1][d];
        float d00 = a0 - b0, d01 = a0 - b1, d10 = a1 - b0, d11 = a1 - b1;
        pt[0][0] += d00 * d00; pt[0][1] += d01 * d01;
        pt[1][0] += d10 * d10; pt[1][1] += d11 * d11;
    }
    #pragma unroll
    for (int a = 0; a < 2; a++) {
        int i = i0 + ty * 2 + a;
        #pragma unroll
        for (int b = 0; b < 2; b++) {
            int j = j0 + tx * 2 + b;
            float m = mask[i * N + j];
            g_logits[(long)h * NN + i * N + j] =
                QK_SCALE * dot[a][b] - 0.5f * hw * pt[a][b] + INFV * (m - 1.0f);
        }
    }
}

// ---------------- fused z kernel: bias + logits + exp + o_pair (e pre-duplicated) ----------------
__global__ void __launch_bounds__(256, 3) k_zfused(const float* __restrict__ z,
                                                   const float* __restrict__ wb,
                                                   const float* __restrict__ bb) {
    extern __shared__ float sm[];
    float* s_z    = sm + ZOFF_SZ;     // [64][132]
    float* wbT    = sm + ZOFF_WBT;    // [12][128], pre-scaled by sqrt(1/3)
    float* qkt    = sm + ZOFF_QKT;    // [12][64]
    unsigned long long* e_dup = reinterpret_cast<unsigned long long*>(sm + ZOFF_ESH); // [64][12] of (e,e)
    float* rbias  = sm + ZOFF_RBIAS;  // [4][12][64]
    float* s_S    = sm + ZOFF_S;      // [12] running row sums
    float* s_bsbb = sm + ZOFF_BB;

    int i = blockIdx.x;
    int t = threadIdx.x;
    const float BS = 0.57735026918962576f; // sqrt(1/3)

    for (int idx = t; idx < 12 * 128; idx += 256) {
        int h = idx >> 7, c = idx & 127;
        wbT[idx] = BS * wb[c * 12 + h];
    }
    if (t < 12) {
        s_bsbb[t] = BS * bb[t];
        s_S[t] = 0.0f;
    }

    int rg = t & 63, cq = t >> 6;     // bias mapping
    int c2 = t & 63, g = t >> 6;      // o_pair mapping

    unsigned long long acc[12];
    #pragma unroll
    for (int h = 0; h < 12; h++) acc[h] = 0ull;

    for (int tile = 0; tile < 12; tile++) {
        __syncthreads();   // covers init (tile 0); protects s_z/e_dup/qkt from prior readers
        // stage z tile (coalesced)
        #pragma unroll
        for (int r = 0; r < 8; r++) {
            int idx = t + 256 * r;
            int row = idx >> 5, c4 = idx & 31;
            float4 v = *reinterpret_cast<const float4*>(
                &z[((long)i * N + tile * 64 + row) * CZ + c4 * 4]);
            *reinterpret_cast<float4*>(&s_z[row * 132 + c4 * 4]) = v;
        }
        // stage qk terms tile
        if (t < 192) {
            int h = t >> 4, q4 = t & 15;
            float4 v = *reinterpret_cast<const float4*>(
                &g_logits[(long)h * NN + i * N + tile * 64 + q4 * 4]);
            *reinterpret_cast<float4*>(&qkt[h * 64 + q4 * 4]) = v;
        }
        __syncthreads();

        // bias partial dot over this thread's column quarter, all 12 heads
        {
            unsigned long long bacc[12];
            #pragma unroll
            for (int h = 0; h < 12; h++) bacc[h] = 0ull;
            const float* zr = &s_z[rg * 132 + cq * 32];
            #pragma unroll
            for (int c4 = 0; c4 < 8; c4++) {
                ulonglong2 zz = *reinterpret_cast<const ulonglong2*>(&zr[c4 * 4]);
                #pragma unroll
                for (int h = 0; h < 12; h++) {
                    ulonglong2 ww = *reinterpret_cast<const ulonglong2*>(&wbT[h * 128 + cq * 32 + c4 * 4]);
                    fma2(bacc[h], zz.x, ww.x);
                    fma2(bacc[h], zz.y, ww.y);
                }
            }
            #pragma unroll
            for (int h = 0; h < 12; h++)
                rbias[cq * 768 + h * 64 + rg] = hsum2(bacc[h]);
        }
        __syncthreads();

        // logits + exp + row-sum partials: 768 (h,row) items over 256 threads (warp-coherent rows)
        #pragma unroll
        for (int k = 0; k < 3; k++) {
            int h2 = (t >> 6) + 4 * k;
            int r2 = t & 63;
            float l = rbias[0 * 768 + h2 * 64 + r2]
                    + rbias[1 * 768 + h2 * 64 + r2]
                    + rbias[2 * 768 + h2 * 64 + r2]
                    + rbias[3 * 768 + h2 * 64 + r2]
                    + s_bsbb[h2] + qkt[h2 * 64 + r2];
            float e = __expf(l);
            e_dup[r2 * 12 + h2] = pk2(e, e);
            g_logits[(long)h2 * NN + i * N + tile * 64 + r2] = e;
            float ss = e;
            #pragma unroll
            for (int off = 16; off; off >>= 1)
                ss += __shfl_xor_sync(0xffffffffu, ss, off);
            if ((t & 31) == 0) atomicAdd(&s_S[h2], ss);
        }
        __syncthreads();

        // o_pair accumulate from smem tile (e pre-duplicated; 16B-aligned head-pair loads)
        #pragma unroll
        for (int jj = 0; jj < 16; jj++) {
            int j = jj * 4 + g;
            unsigned long long zz = *reinterpret_cast<const unsigned long long*>(&s_z[j * 132 + c2 * 2]);
            const ulonglong2* ep = reinterpret_cast<const ulonglong2*>(&e_dup[j * 12]);
            ulonglong2 e01 = ep[0];
            ulonglong2 e23 = ep[1];
            ulonglong2 e45 = ep[2];
            fma2(acc[0],  zz, e01.x);
            fma2(acc[1],  zz, e01.y);
            fma2(acc[2],  zz, e23.x);
            fma2(acc[3],  zz, e23.y);
            fma2(acc[4],  zz, e45.x);
            fma2(acc[5],  zz, e45.y);
            ulonglong2 e67 = ep[3];
            ulonglong2 e89 = ep[4];
            ulonglong2 eab = ep[5];
            fma2(acc[6],  zz, e67.x);
            fma2(acc[7],  zz, e67.y);
            fma2(acc[8],  zz, e89.x);
            fma2(acc[9],  zz, e89.y);
            fma2(acc[10], zz, eab.x);
            fma2(acc[11], zz, eab.y);
        }
    }

    // epilogue: reduce 4 j-group partials via smem (alias s_z), normalize, store
    __syncthreads();
    unsigned long long* rbuf = reinterpret_cast<unsigned long long*>(s_z);  // 4*12*64 ull
    #pragma unroll
    for (int h = 0; h < 12; h++)
        rbuf[g * 768 + h * 64 + c2] = acc[h];
    __syncthreads();
    #pragma unroll
    for (int r = 0; r < 3; r++) {
        int idx = t + 256 * r;          // 0..767
        int h = idx >> 6, cc = idx & 63;
        float sx = 0.f, sy = 0.f;
        #pragma unroll
        for (int gg = 0; gg < 4; gg++) {
            float x, y;
            unpk2(rbuf[gg * 768 + h * 64 + cc], x, y);
            sx += x; sy += y;
        }
        float inv = 1.0f / s_S[h];
        *reinterpret_cast<float2*>(&g_cat[(long)i * CAT_DIM + 576 + h * 128 + cc * 2]) =
            make_float2(sx * inv, sy * inv);
    }
    if (t < 12)
        g_sinv[t * N + i] = 1.0f / s_S[t];
}

// ---------------- o = a@v, o_pt_global = a@v_pts (256 thr, measured-good version) ----------------
__global__ void k_av() {
    __shared__ float a_sh[32][64];
    __shared__ float vv_sh[64][41];
    int h = blockIdx.y;
    int i0 = blockIdx.x * 32;
    int tid = threadIdx.x;
    int i_local = tid >> 3;
    int cbase = tid & 7;
    float acc[5] = {};
    for (int j0 = 0; j0 < N; j0 += 64) {
        #pragma unroll
        for (int r = 0; r < 8; r++) {
            int idx = tid + 256 * r;
            int ii = idx >> 6, jj = idx & 63;
            a_sh[ii][jj] = g_logits[(long)h * NN + (i0 + ii) * N + j0 + jj];
        }
        #pragma unroll
        for (int r = 0; r < 10; r++) {
            int idx = tid + 256 * r;
            int jj = idx / 40, col = idx % 40;
            float val;
            if (col < 16) val = g_kvlin[(j0 + jj) * KV_COLS + h * 32 + 16 + col];
            else          val = g_vpts[(j0 + jj) * 288 + h * 24 + (col - 16)];
            vv_sh[jj][col] = val;
        }
        __syncthreads();
        #pragma unroll 4
        for (int jj = 0; jj < 64; jj++) {
            float av = a_sh[i_local][jj];
            #pragma unroll
            for (int k = 0; k < 5; k++) acc[k] += av * vv_sh[jj][cbase + 8 * k];
        }
        __syncthreads();
    }
    int i = i0 + i_local;
    float inv = g_sinv[h * N + i];
    #pragma unroll
    for (int k = 0; k < 5; k++) {
        acc[k] *= inv;
        int col = cbase + 8 * k;
        if (col < 16) g_cat[(long)i * CAT_DIM + h * 16 + col] = acc[k];
        else          g_optg[i * 288 + h * 24 + (col - 16)] = acc[k];
    }
}

// ---------------- o_pt: inverse frame + norm ----------------
__global__ void k_ptfinish(const float* __restrict__ rot, const float* __restrict__ trans) {
    int idx = blockIdx.x * 256 + threadIdx.x;
    if (idx >= N * H * PV) return;
    int i = idx / (H * PV);
    int hp = idx % (H * PV);
    int h = hp / PV, pv = hp % PV;
    float g[3];
    #pragma unroll
    for (int d = 0; d < 3; d++)
        g[d] = g_optg[i * 288 + h * 24 + pv * 3 + d] - trans[i * 3 + d];
    const float* R = rot + i * 9;
    float n2 = EPSV;
    #pragma unroll
    for (int jd = 0; jd < 3; jd++) {
        float loc = R[0 * 3 + jd] * g[0] + R[1 * 3 + jd] * g[1] + R[2 * 3 + jd] * g[2];
        g_cat[(long)i * CAT_DIM + 192 + 96 * jd + hp] = loc;
        n2 += loc * loc;
    }
    g_cat[(long)i * CAT_DIM + 480 + hp] = sqrtf(n2);
}

// ---------------- launch ----------------
extern "C" void kernel_launch(void* const* d_in, const int* in_sizes, int n_in,
                              void* d_out, int out_size) {
    const float* s     = (const float*)d_in[0];
    const float* z     = (const float*)d_in[1];
    const float* rot   = (const float*)d_in[2];
    const float* trans = (const float*)d_in[3];
    const float* mask  = (const float*)d_in[4];
    const float* wq    = (const float*)d_in[5];
    const float* bq    = (const float*)d_in[6];
    const float* wkv   = (const float*)d_in[7];
    const float* bkv   = (const float*)d_in[8];
    const float* wqp   = (const float*)d_in[9];
    const float* bqp   = (const float*)d_in[10];
    const float* wkvp  = (const float*)d_in[11];
    const float* bkvp  = (const float*)d_in[12];
    const float* wb    = (const float*)d_in[13];
    const float* bb    = (const float*)d_in[14];
    const float* hwts  = (const float*)d_in[15];
    const float* wout  = (const float*)d_in[16];
    const float* bout  = (const float*)d_in[17];
    float* out = (float*)d_out;

    cudaFuncSetAttribute(k_zfused, cudaFuncAttributeMaxDynamicSharedMemorySize, ZF_SMEM_BYTES);

    // projections + points
    k_proj<<<dim3(19, 24), 256>>>(s, wq, bq, wkv, bkv, wqp, bqp, wkvp, bkvp);
    k_points_all<<<(N * 192 + 255) / 256, 256>>>(rot, trans);
    // qk + pt + mask terms -> g_logits (pure write)
    k_qk<<<dim3(N / 32, N / 32, H), dim3(16, 16)>>>(mask, hwts);
    // fused: bias + logits + exp + o_pair; SINGLE z DRAM pass
    k_zfused<<<N, 256, ZF_SMEM_BYTES>>>(z, wb, bb);
    // a @ [v, v_pts]; row-normalize at the end
    k_av<<<dim3(N / 32, H), 256>>>();
    // invert frames + norms
    k_ptfinish<<<(N * H * PV + 255) / 256, 256>>>(rot, trans);
    // output projection
    k_outgemm<<<dim3(6, 24), 256>>>(wout, bout, out);
}

// round 13
// speedup vs baseline: 1.1250x; 1.1250x over previous
#include <cuda_runtime.h>
#include <math.h>

#define N    768
#define CN   384
#define CZ   128
#define CC   16
#define H    12
#define PQ   4
#define PV   8
#define NN   (N*N)                 // 589824
#define HC   (H*CC)                // 192
#define KV_COLS (2*HC)             // 384
#define QP_COLS (H*PQ*3)           // 144
#define KVP_COLS (H*12*3)          // 432
#define CAT_DIM (H*(CZ+CC+PV*4))   // 2112
#define INFV 100000.0f
#define EPSV 1e-8f

// ---- k_zfused smem layout (floats), double-buffered z + qkt ----
#define ZOFF_SZ0   0                      // 64*132 = 8448  (buf0; aliased as rbuf in epilogue)
#define ZOFF_SZ1   8448                   // 8448            (buf1)
#define ZOFF_WBT   16896                  // 12*128 = 1536
#define ZOFF_QKT0  18432                  // 12*64 = 768
#define ZOFF_QKT1  19200                  // 768
#define ZOFF_ESH   19968                  // 64*12 = 768
#define ZOFF_RBIAS 20736                  // 4*12*64 = 3072
#define ZOFF_S     23808                  // 12
#define ZOFF_BB    23820                  // 12
#define ZF_SMEM_FLOATS 23840
#define ZF_SMEM_BYTES (ZF_SMEM_FLOATS*4)  // 95360

// ---------------- scratch ----------------
__device__ float g_qlin  [N*HC];
__device__ float g_kvlin [N*KV_COLS];
__device__ float g_qplin [N*QP_COLS];
__device__ float g_kvplin[N*KVP_COLS];
__device__ float g_qpts  [N*H*PQ*3];
__device__ float g_kpts  [N*H*PQ*3];
__device__ float g_vpts  [N*H*PV*3];
__device__ float g_logits[H*NN];        // qk+pt+mask terms, then UNNORMALIZED exp(a)
__device__ float g_sinv  [H*N];         // 1/rowsum per (h, i)
__device__ float g_optg  [N*H*PV*3];
__device__ float g_cat   [N*CAT_DIM];

// ---------------- f32x2 packed helpers ----------------
__device__ __forceinline__ void fma2(unsigned long long& acc, unsigned long long a, unsigned long long b) {
    asm("fma.rn.f32x2 %0, %1, %2, %0;" : "+l"(acc) : "l"(a), "l"(b));
}
__device__ __forceinline__ unsigned long long pk2(float a, float b) {
    unsigned long long r; asm("mov.b64 %0, {%1,%2};" : "=l"(r) : "f"(a), "f"(b)); return r;
}
__device__ __forceinline__ float hsum2(unsigned long long v) {
    float x, y; asm("mov.b64 {%0,%1}, %2;" : "=f"(x), "=f"(y) : "l"(v)); return x + y;
}
__device__ __forceinline__ void unpk2(unsigned long long v, float& x, float& y) {
    asm("mov.b64 {%0,%1}, %2;" : "=f"(x), "=f"(y) : "l"(v));
}
// ---------------- cp.async helpers ----------------
__device__ __forceinline__ void cp16(unsigned int smem_addr, const void* gptr) {
    asm volatile("cp.async.cg.shared.global [%0], [%1], 16;" :: "r"(smem_addr), "l"(gptr));
}
#define CP_COMMIT() asm volatile("cp.async.commit_group;" ::: "memory")
#define CP_WAIT1()  asm volatile("cp.async.wait_group 1;" ::: "memory")

// ---------------- tiled GEMM body: out = A@W + bias ----------------
__device__ __forceinline__ void gemm_tile(const float* __restrict__ A, const float* __restrict__ W,
                                          const float* __restrict__ bias, float* __restrict__ out,
                                          int K, int Nc, int row0, int col0) {
    __shared__ __align__(16) float As[32][33];
    __shared__ __align__(16) float Ws[32][64];
    int t = threadIdx.x;
    int tx = t & 15, ty = t >> 4;
    int lm = t >> 3;
    int lk4 = t & 7;
    float acc[2][4] = {};
    for (int k0 = 0; k0 < K; k0 += 32) {
        float4 a4 = *reinterpret_cast<const float4*>(&A[(long)(row0 + lm) * K + k0 + lk4 * 4]);
        As[lk4 * 4 + 0][lm] = a4.x;
        As[lk4 * 4 + 1][lm] = a4.y;
        As[lk4 * 4 + 2][lm] = a4.z;
        As[lk4 * 4 + 3][lm] = a4.w;
        #pragma unroll
        for (int r = 0; r < 2; r++) {
            int li = t + 256 * r;
            int kk = li >> 4, c4 = li & 15;
            int col = col0 + c4 * 4;
            float4 w4 = make_float4(0.f, 0.f, 0.f, 0.f);
            if (col < Nc)
                w4 = *reinterpret_cast<const float4*>(&W[(long)(k0 + kk) * Nc + col]);
            *reinterpret_cast<float4*>(&Ws[kk][c4 * 4]) = w4;
        }
        __syncthreads();
        #pragma unroll
        for (int kk = 0; kk < 32; kk++) {
            float a0 = As[kk][ty * 2 + 0];
            float a1 = As[kk][ty * 2 + 1];
            float4 w = *reinterpret_cast<const float4*>(&Ws[kk][tx * 4]);
            acc[0][0] += a0 * w.x; acc[0][1] += a0 * w.y; acc[0][2] += a0 * w.z; acc[0][3] += a0 * w.w;
            acc[1][0] += a1 * w.x; acc[1][1] += a1 * w.y; acc[1][2] += a1 * w.z; acc[1][3] += a1 * w.w;
        }
        __syncthreads();
    }
    int col = col0 + tx * 4;
    if (col < Nc) {
        float4 b4 = *reinterpret_cast<const float4*>(&bias[col]);
        #pragma unroll
        for (int r = 0; r < 2; r++) {
            int row = row0 + ty * 2 + r;
            float4 o;
            o.x = acc[r][0] + b4.x; o.y = acc[r][1] + b4.y;
            o.z = acc[r][2] + b4.z; o.w = acc[r][3] + b4.w;
            *reinterpret_cast<float4*>(&out[(long)row * Nc + col]) = o;
        }
    }
}

__global__ void k_proj(const float* __restrict__ s,
                       const float* __restrict__ wq,  const float* __restrict__ bq,
                       const float* __restrict__ wkv, const float* __restrict__ bkv,
                       const float* __restrict__ wqp, const float* __restrict__ bqp,
                       const float* __restrict__ wkvp,const float* __restrict__ bkvp) {
    int bx = blockIdx.x;
    const float* W; const float* b; float* out; int Nc; int ct;
    if (bx < 3)       { W = wq;   b = bq;   out = g_qlin;   Nc = HC;       ct = bx; }
    else if (bx < 9)  { W = wkv;  b = bkv;  out = g_kvlin;  Nc = KV_COLS;  ct = bx - 3; }
    else if (bx < 12) { W = wqp;  b = bqp;  out = g_qplin;  Nc = QP_COLS;  ct = bx - 9; }
    else              { W = wkvp; b = bkvp; out = g_kvplin; Nc = KVP_COLS; ct = bx - 12; }
    gemm_tile(s, W, b, out, CN, Nc, blockIdx.y * 32, ct * 64);
}

__global__ void k_outgemm(const float* __restrict__ W, const float* __restrict__ bias,
                          float* __restrict__ out) {
    gemm_tile(g_cat, W, bias, out, CAT_DIM, CN, blockIdx.y * 32, blockIdx.x * 64);
}

// ---------------- point construction ----------------
__global__ void k_points_all(const float* __restrict__ rot, const float* __restrict__ trans) {
    int idx = blockIdx.x * 256 + threadIdx.x;
    if (idx >= N * 192) return;
    int i = idx / 192, p = idx % 192;
    float l0, l1, l2;
    if (p < 48) {
        const float* lin = g_qplin + i * QP_COLS;
        l0 = lin[p]; l1 = lin[48 + p]; l2 = lin[96 + p];
    } else {
        const float* lin = g_kvplin + i * KVP_COLS;
        int pp = p - 48;
        l0 = lin[pp]; l1 = lin[144 + pp]; l2 = lin[288 + pp];
    }
    const float* R = rot + i * 9;
    float o[3];
    #pragma unroll
    for (int d = 0; d < 3; d++)
        o[d] = R[d * 3 + 0] * l0 + R[d * 3 + 1] * l1 + R[d * 3 + 2] * l2 + trans[i * 3 + d];
    if (p < 48) {
        int h = p / PQ, tt = p % PQ;
        #pragma unroll
        for (int d = 0; d < 3; d++) g_qpts[i * 144 + h * 12 + tt * 3 + d] = o[d];
    } else {
        int pp = p - 48;
        int h = pp / 12, tt = pp % 12;
        if (tt < PQ) {
            #pragma unroll
            for (int d = 0; d < 3; d++) g_kpts[i * 144 + h * 12 + tt * 3 + d] = o[d];
        } else {
            #pragma unroll
            for (int d = 0; d < 3; d++) g_vpts[i * 288 + h * 24 + (tt - PQ) * 3 + d] = o[d];
        }
    }
}

// ---------------- qk + pt_att + mask terms (pure WRITE into g_logits) ----------------
__global__ void k_qk(const float* __restrict__ mask, const float* __restrict__ hwts) {
    __shared__ float qs[32][17], ks[32][17];
    __shared__ float qps[32][13], kps[32][13];
    int h = blockIdx.z;
    int i0 = blockIdx.y * 32, j0 = blockIdx.x * 32;
    int tx = threadIdx.x, ty = threadIdx.y;
    int tid = ty * 16 + tx;
    for (int r = 0; r < 2; r++) {
        int idx = tid + 256 * r;
        int ii = idx >> 4, c = idx & 15;
        qs[ii][c] = g_qlin[(i0 + ii) * HC + h * 16 + c];
        ks[ii][c] = g_kvlin[(j0 + ii) * KV_COLS + h * 32 + c];
        if (idx < 384) {
            int i2 = idx / 12, d = idx % 12;
            qps[i2][d] = g_qpts[(i0 + i2) * 144 + h * 12 + d];
            kps[i2][d] = g_kpts[(j0 + i2) * 144 + h * 12 + d];
        }
    }
    __syncthreads();
    float w = hwts[h];
    float hw = logf(1.0f + expf(w)) * 0.13608276348795434f; // softplus * sqrt(1/54)
    const float QK_SCALE = 0.14433756729740643f;            // sqrt(1/48)
    float dot[2][2] = {};
    float pt[2][2] = {};
    #pragma unroll
    for (int c = 0; c < 16; c++) {
        float a0 = qs[ty * 2][c], a1 = qs[ty * 2 + 1][c];
        float b0 = ks[tx * 2][c], b1 = ks[tx * 2 + 1][c];
        dot[0][0] += a0 * b0; dot[0][1] += a0 * b1;
        dot[1][0] += a1 * b0; dot[1][1] += a1 * b1;
    }
    #pragma unroll
    for (int d = 0; d < 12; d++) {
        float a0 = qps[ty * 2][d], a1 = qps[ty * 2 + 1][d];
        float b0 = kps[tx * 2][d], b1 = kps[tx * 2 + 1][d];
        float d00 = a0 - b0, d01 = a0 - b1, d10 = a1 - b0, d11 = a1 - b1;
        pt[0][0] += d00 * d00; pt[0][1] += d01 * d01;
        pt[1][0] += d10 * d10; pt[1][1] += d11 * d11;
    }
    #pragma unroll
    for (int a = 0; a < 2; a++) {
        int i = i0 + ty * 2 + a;
        #pragma unroll
        for (int b = 0; b < 2; b++) {
            int j = j0 + tx * 2 + b;
            float m = mask[i * N + j];
            g_logits[(long)h * NN + i * N + j] =
                QK_SCALE * dot[a][b] - 0.5f * hw * pt[a][b] + INFV * (m - 1.0f);
        }
    }
}

// ---------------- fused z kernel: R9 compute phases + cp.async double-buffered staging ----------------
__global__ void __launch_bounds__(256, 2) k_zfused(const float* __restrict__ z,
                                                   const float* __restrict__ wb,
                                                   const float* __restrict__ bb) {
    extern __shared__ float sm[];
    float* wbT    = sm + ZOFF_WBT;    // [12][128], pre-scaled by sqrt(1/3)
    float* e_sh   = sm + ZOFF_ESH;    // [64][12]
    float* rbias  = sm + ZOFF_RBIAS;  // [4][12][64]
    float* s_S    = sm + ZOFF_S;      // [12]
    float* s_bsbb = sm + ZOFF_BB;

    int i = blockIdx.x;
    int t = threadIdx.x;
    const float BS = 0.57735026918962576f; // sqrt(1/3)
    unsigned int sbase = (unsigned int)__cvta_generic_to_shared(sm);

    for (int idx = t; idx < 12 * 128; idx += 256) {
        int h = idx >> 7, c = idx & 127;
        wbT[idx] = BS * wb[c * 12 + h];
    }
    if (t < 12) {
        s_bsbb[t] = BS * bb[t];
        s_S[t] = 0.0f;
    }

    int rg = t & 63, cq = t >> 6;     // bias mapping
    int c2 = t & 63, g = t >> 6;      // o_pair mapping

    // prefetch helper offsets for this thread
    int pf_row[8], pf_c4[8];
    #pragma unroll
    for (int r = 0; r < 8; r++) {
        int idx = t + 256 * r;
        pf_row[r] = idx >> 5;
        pf_c4[r]  = idx & 31;
    }
    int qh = t >> 4, qq4 = t & 15;    // qkt prefetch mapping (t < 192)

    // prologue: prefetch tile 0 into buf0
    #pragma unroll
    for (int r = 0; r < 8; r++) {
        cp16(sbase + (ZOFF_SZ0 + pf_row[r] * 132 + pf_c4[r] * 4) * 4,
             &z[((long)i * N + 0 * 64 + pf_row[r]) * CZ + pf_c4[r] * 4]);
    }
    if (t < 192)
        cp16(sbase + (ZOFF_QKT0 + qh * 64 + qq4 * 4) * 4,
             &g_logits[(long)qh * NN + i * N + 0 * 64 + qq4 * 4]);
    CP_COMMIT();

    unsigned long long acc[12];
    #pragma unroll
    for (int h = 0; h < 12; h++) acc[h] = 0ull;

    for (int tile = 0; tile < 12; tile++) {
        int cur = tile & 1;
        float* s_z = sm + (cur ? ZOFF_SZ1 : ZOFF_SZ0);
        float* qkt = sm + (cur ? ZOFF_QKT1 : ZOFF_QKT0);

        __syncthreads();   // o_pair(t-1) / epilogue buffers released; init visible (tile 0)

        // prefetch next tile into alternate buffer
        if (tile < 11) {
            int nxt = (tile + 1) & 1;
            unsigned int zoff = nxt ? ZOFF_SZ1 : ZOFF_SZ0;
            unsigned int qoff = nxt ? ZOFF_QKT1 : ZOFF_QKT0;
            #pragma unroll
            for (int r = 0; r < 8; r++) {
                cp16(sbase + (zoff + pf_row[r] * 132 + pf_c4[r] * 4) * 4,
                     &z[((long)i * N + (tile + 1) * 64 + pf_row[r]) * CZ + pf_c4[r] * 4]);
            }
            if (t < 192)
                cp16(sbase + (qoff + qh * 64 + qq4 * 4) * 4,
                     &g_logits[(long)qh * NN + i * N + (tile + 1) * 64 + qq4 * 4]);
        }
        CP_COMMIT();
        CP_WAIT1();        // current tile's group complete
        __syncthreads();   // visible to all warps

        // bias partial dot over this thread's column quarter, all 12 heads
        {
            unsigned long long bacc[12];
            #pragma unroll
            for (int h = 0; h < 12; h++) bacc[h] = 0ull;
            const float* zr = &s_z[rg * 132 + cq * 32];
            #pragma unroll
            for (int c4 = 0; c4 < 8; c4++) {
                ulonglong2 zz = *reinterpret_cast<const ulonglong2*>(&zr[c4 * 4]);
                #pragma unroll
                for (int h = 0; h < 12; h++) {
                    ulonglong2 ww = *reinterpret_cast<const ulonglong2*>(&wbT[h * 128 + cq * 32 + c4 * 4]);
                    fma2(bacc[h], zz.x, ww.x);
                    fma2(bacc[h], zz.y, ww.y);
                }
            }
            #pragma unroll
            for (int h = 0; h < 12; h++)
                rbias[cq * 768 + h * 64 + rg] = hsum2(bacc[h]);
        }
        __syncthreads();

        // logits + exp + row-sum partials: 768 (h,row) items over 256 threads
        #pragma unroll
        for (int k = 0; k < 3; k++) {
            int h2 = (t >> 6) + 4 * k;
            int r2 = t & 63;
            float l = rbias[0 * 768 + h2 * 64 + r2]
                    + rbias[1 * 768 + h2 * 64 + r2]
                    + rbias[2 * 768 + h2 * 64 + r2]
                    + rbias[3 * 768 + h2 * 64 + r2]
                    + s_bsbb[h2] + qkt[h2 * 64 + r2];
            float e = __expf(l);
            e_sh[r2 * 12 + h2] = e;
            g_logits[(long)h2 * NN + i * N + tile * 64 + r2] = e;
            float ss = e;
            #pragma unroll
            for (int off = 16; off; off >>= 1)
                ss += __shfl_xor_sync(0xffffffffu, ss, off);
            if ((t & 31) == 0) atomicAdd(&s_S[h2], ss);
        }
        __syncthreads();

        // o_pair accumulate from smem tile
        #pragma unroll
        for (int jj = 0; jj < 16; jj++) {
            int j = jj * 4 + g;
            unsigned long long zz = *reinterpret_cast<const unsigned long long*>(&s_z[j * 132 + c2 * 2]);
            const float4* ep = reinterpret_cast<const float4*>(&e_sh[j * 12]);
            float4 e0 = ep[0], e1 = ep[1], e2 = ep[2];
            fma2(acc[0],  zz, pk2(e0.x, e0.x));
            fma2(acc[1],  zz, pk2(e0.y, e0.y));
            fma2(acc[2],  zz, pk2(e0.z, e0.z));
            fma2(acc[3],  zz, pk2(e0.w, e0.w));
            fma2(acc[4],  zz, pk2(e1.x, e1.x));
            fma2(acc[5],  zz, pk2(e1.y, e1.y));
            fma2(acc[6],  zz, pk2(e1.z, e1.z));
            fma2(acc[7],  zz, pk2(e1.w, e1.w));
            fma2(acc[8],  zz, pk2(e2.x, e2.x));
            fma2(acc[9],  zz, pk2(e2.y, e2.y));
            fma2(acc[10], zz, pk2(e2.z, e2.z));
            fma2(acc[11], zz, pk2(e2.w, e2.w));
        }
    }

    // epilogue: reduce 4 j-group partials via smem (alias buf0), normalize, store
    __syncthreads();
    unsigned long long* rbuf = reinterpret_cast<unsigned long long*>(sm + ZOFF_SZ0);  // 4*12*64 ull
    #pragma unroll
    for (int h = 0; h < 12; h++)
        rbuf[g * 768 + h * 64 + c2] = acc[h];
    __syncthreads();
    #pragma unroll
    for (int r = 0; r < 3; r++) {
        int idx = t + 256 * r;          // 0..767
        int h = idx >> 6, cc = idx & 63;
        float sx = 0.f, sy = 0.f;
        #pragma unroll
        for (int gg = 0; gg < 4; gg++) {
            float x, y;
            unpk2(rbuf[gg * 768 + h * 64 + cc], x, y);
            sx += x; sy += y;
        }
        float inv = 1.0f / s_S[h];
        *reinterpret_cast<float2*>(&g_cat[(long)i * CAT_DIM + 576 + h * 128 + cc * 2]) =
            make_float2(sx * inv, sy * inv);
    }
    if (t < 12)
        g_sinv[t * N + i] = 1.0f / s_S[t];
}

// ---------------- o = a@v, o_pt_global = a@v_pts (256 thr, measured-good version) ----------------
__global__ void k_av() {
    __shared__ float a_sh[32][64];
    __shared__ float vv_sh[64][41];
    int h = blockIdx.y;
    int i0 = blockIdx.x * 32;
    int tid = threadIdx.x;
    int i_local = tid >> 3;
    int cbase = tid & 7;
    float acc[5] = {};
    for (int j0 = 0; j0 < N; j0 += 64) {
        #pragma unroll
        for (int r = 0; r < 8; r++) {
            int idx = tid + 256 * r;
            int ii = idx >> 6, jj = idx & 63;
            a_sh[ii][jj] = g_logits[(long)h * NN + (i0 + ii) * N + j0 + jj];
        }
        #pragma unroll
        for (int r = 0; r < 10; r++) {
            int idx = tid + 256 * r;
            int jj = idx / 40, col = idx % 40;
            float val;
            if (col < 16) val = g_kvlin[(j0 + jj) * KV_COLS + h * 32 + 16 + col];
            else          val = g_vpts[(j0 + jj) * 288 + h * 24 + (col - 16)];
            vv_sh[jj][col] = val;
        }
        __syncthreads();
        #pragma unroll 4
        for (int jj = 0; jj < 64; jj++) {
            float av = a_sh[i_local][jj];
            #pragma unroll
            for (int k = 0; k < 5; k++) acc[k] += av * vv_sh[jj][cbase + 8 * k];
        }
        __syncthreads();
    }
    int i = i0 + i_local;
    float inv = g_sinv[h * N + i];
    #pragma unroll
    for (int k = 0; k < 5; k++) {
        acc[k] *= inv;
        int col = cbase + 8 * k;
        if (col < 16) g_cat[(long)i * CAT_DIM + h * 16 + col] = acc[k];
        else          g_optg[i * 288 + h * 24 + (col - 16)] = acc[k];
    }
}

// ---------------- o_pt: inverse frame + norm ----------------
__global__ void k_ptfinish(const float* __restrict__ rot, const float* __restrict__ trans) {
    int idx = blockIdx.x * 256 + threadIdx.x;
    if (idx >= N * H * PV) return;
    int i = idx / (H * PV);
    int hp = idx % (H * PV);
    int h = hp / PV, pv = hp % PV;
    float g[3];
    #pragma unroll
    for (int d = 0; d < 3; d++)
        g[d] = g_optg[i * 288 + h * 24 + pv * 3 + d] - trans[i * 3 + d];
    const float* R = rot + i * 9;
    float n2 = EPSV;
    #pragma unroll
    for (int jd = 0; jd < 3; jd++) {
        float loc = R[0 * 3 + jd] * g[0] + R[1 * 3 + jd] * g[1] + R[2 * 3 + jd] * g[2];
        g_cat[(long)i * CAT_DIM + 192 + 96 * jd + hp] = loc;
        n2 += loc * loc;
    }
    g_cat[(long)i * CAT_DIM + 480 + hp] = sqrtf(n2);
}

// ---------------- launch ----------------
extern "C" void kernel_launch(void* const* d_in, const int* in_sizes, int n_in,
                              void* d_out, int out_size) {
    const float* s     = (const float*)d_in[0];
    const float* z     = (const float*)d_in[1];
    const float* rot   = (const float*)d_in[2];
    const float* trans = (const float*)d_in[3];
    const float* mask  = (const float*)d_in[4];
    const float* wq    = (const float*)d_in[5];
    const float* bq    = (const float*)d_in[6];
    const float* wkv   = (const float*)d_in[7];
    const float* bkv   = (const float*)d_in[8];
    const float* wqp   = (const float*)d_in[9];
    const float* bqp   = (const float*)d_in[10];
    const float* wkvp  = (const float*)d_in[11];
    const float* bkvp  = (const float*)d_in[12];
    const float* wb    = (const float*)d_in[13];
    const float* bb    = (const float*)d_in[14];
    const float* hwts  = (const float*)d_in[15];
    const float* wout  = (const float*)d_in[16];
    const float* bout  = (const float*)d_in[17];
    float* out = (float*)d_out;

    cudaFuncSetAttribute(k_zfused, cudaFuncAttributeMaxDynamicSharedMemorySize, ZF_SMEM_BYTES);

    // projections + points
    k_proj<<<dim3(19, 24), 256>>>(s, wq, bq, wkv, bkv, wqp, bqp, wkvp, bkvp);
    k_points_all<<<(N * 192 + 255) / 256, 256>>>(rot, trans);
    // qk + pt + mask terms -> g_logits (pure write)
    k_qk<<<dim3(N / 32, N / 32, H), dim3(16, 16)>>>(mask, hwts);
    // fused: bias + logits + exp + o_pair; SINGLE z DRAM pass, cp.async pipelined
    k_zfused<<<N, 256, ZF_SMEM_BYTES>>>(z, wb, bb);
    // a @ [v, v_pts]; row-normalize at the end
    k_av<<<dim3(N / 32, H), 256>>>();
    // invert frames + norms
    k_ptfinish<<<(N * H * PV + 255) / 256, 256>>>(rot, trans);
    // output projection
    k_outgemm<<<dim3(6, 24), 256>>>(wout, bout, out);
}

// round 14
// speedup vs baseline: 1.3040x; 1.1592x over previous
#include <cuda_runtime.h>
#include <math.h>

#define N    768
#define CN   384
#define CZ   128
#define CC   16
#define H    12
#define PQ   4
#define PV   8
#define NN   (N*N)                 // 589824
#define HC   (H*CC)                // 192
#define KV_COLS (2*HC)             // 384
#define QP_COLS (H*PQ*3)           // 144
#define KVP_COLS (H*12*3)          // 432
#define CAT_DIM (H*(CZ+CC+PV*4))   // 2112
#define INFV 100000.0f
#define EPSV 1e-8f

// ---- k_zfused smem layout (floats), double-buffered z + qkt ----
#define ZOFF_SZ0   0                      // 64*132 = 8448  (buf0; aliased as rbuf in epilogue)
#define ZOFF_SZ1   8448                   // 8448            (buf1)
#define ZOFF_WBT   16896                  // 12*128 = 1536
#define ZOFF_QKT0  18432                  // 12*64 = 768
#define ZOFF_QKT1  19200                  // 768
#define ZOFF_ESH   19968                  // 64*12 = 768
#define ZOFF_RBIAS 20736                  // 4*12*64 = 3072
#define ZOFF_S     23808                  // 12
#define ZOFF_BB    23820                  // 12
#define ZF_SMEM_FLOATS 23840
#define ZF_SMEM_BYTES (ZF_SMEM_FLOATS*4)  // 95360

// ---------------- scratch ----------------
__device__ float g_qlin  [N*HC];
__device__ float g_kvlin [N*KV_COLS];
__device__ float g_qplin [N*QP_COLS];
__device__ float g_kvplin[N*KVP_COLS];
__device__ float g_qpts  [N*H*PQ*3];
__device__ float g_kpts  [N*H*PQ*3];
__device__ float g_vpts  [N*H*PV*3];
__device__ float g_logits[H*NN];        // qk+pt+mask terms, then UNNORMALIZED exp(a)
__device__ float g_sinv  [H*N];         // 1/rowsum per (h, i)
__device__ float g_cat   [N*CAT_DIM];

// ---------------- f32x2 packed helpers ----------------
__device__ __forceinline__ void fma2(unsigned long long& acc, unsigned long long a, unsigned long long b) {
    asm("fma.rn.f32x2 %0, %1, %2, %0;" : "+l"(acc) : "l"(a), "l"(b));
}
__device__ __forceinline__ unsigned long long pk2(float a, float b) {
    unsigned long long r; asm("mov.b64 %0, {%1,%2};" : "=l"(r) : "f"(a), "f"(b)); return r;
}
__device__ __forceinline__ float hsum2(unsigned long long v) {
    float x, y; asm("mov.b64 {%0,%1}, %2;" : "=f"(x), "=f"(y) : "l"(v)); return x + y;
}
__device__ __forceinline__ void unpk2(unsigned long long v, float& x, float& y) {
    asm("mov.b64 {%0,%1}, %2;" : "=f"(x), "=f"(y) : "l"(v));
}
// ---------------- cp.async helpers ----------------
__device__ __forceinline__ void cp16(unsigned int smem_addr, const void* gptr) {
    asm volatile("cp.async.cg.shared.global [%0], [%1], 16;" :: "r"(smem_addr), "l"(gptr));
}
#define CP_COMMIT() asm volatile("cp.async.commit_group;" ::: "memory")
#define CP_WAIT1()  asm volatile("cp.async.wait_group 1;" ::: "memory")

// ---------------- tiled GEMM body: out = A@W + bias (f32x2 inner loop) ----------------
__device__ __forceinline__ void gemm_tile(const float* __restrict__ A, const float* __restrict__ W,
                                          const float* __restrict__ bias, float* __restrict__ out,
                                          int K, int Nc, int row0, int col0) {
    __shared__ __align__(16) float As[32][34];   // stride 34 (even) for aligned LDS.64
    __shared__ __align__(16) float Ws[32][64];
    int t = threadIdx.x;
    int tx = t & 15, ty = t >> 4;
    int lm = t >> 3;
    int lk4 = t & 7;
    unsigned long long acc00 = 0ull, acc01 = 0ull, acc10 = 0ull, acc11 = 0ull;
    for (int k0 = 0; k0 < K; k0 += 32) {
        float4 a4 = *reinterpret_cast<const float4*>(&A[(long)(row0 + lm) * K + k0 + lk4 * 4]);
        As[lk4 * 4 + 0][lm] = a4.x;
        As[lk4 * 4 + 1][lm] = a4.y;
        As[lk4 * 4 + 2][lm] = a4.z;
        As[lk4 * 4 + 3][lm] = a4.w;
        #pragma unroll
        for (int r = 0; r < 2; r++) {
            int li = t + 256 * r;
            int kk = li >> 4, c4 = li & 15;
            int col = col0 + c4 * 4;
            float4 w4 = make_float4(0.f, 0.f, 0.f, 0.f);
            if (col < Nc)
                w4 = *reinterpret_cast<const float4*>(&W[(long)(k0 + kk) * Nc + col]);
            *reinterpret_cast<float4*>(&Ws[kk][c4 * 4]) = w4;
        }
        __syncthreads();
        #pragma unroll
        for (int kk = 0; kk < 32; kk++) {
            float2 a2 = *reinterpret_cast<const float2*>(&As[kk][ty * 2]);
            ulonglong2 w2 = *reinterpret_cast<const ulonglong2*>(&Ws[kk][tx * 4]);
            unsigned long long a0 = pk2(a2.x, a2.x);
            unsigned long long a1 = pk2(a2.y, a2.y);
            fma2(acc00, a0, w2.x); fma2(acc01, a0, w2.y);
            fma2(acc10, a1, w2.x); fma2(acc11, a1, w2.y);
        }
        __syncthreads();
    }
    int col = col0 + tx * 4;
    if (col < Nc) {
        float4 b4 = *reinterpret_cast<const float4*>(&bias[col]);
        float x, y;
        float4 o;
        unpk2(acc00, x, y); o.x = x + b4.x; o.y = y + b4.y;
        unpk2(acc01, x, y); o.z = x + b4.z; o.w = y + b4.w;
        *reinterpret_cast<float4*>(&out[(long)(row0 + ty * 2 + 0) * Nc + col]) = o;
        unpk2(acc10, x, y); o.x = x + b4.x; o.y = y + b4.y;
        unpk2(acc11, x, y); o.z = x + b4.z; o.w = y + b4.w;
        *reinterpret_cast<float4*>(&out[(long)(row0 + ty * 2 + 1) * Nc + col]) = o;
    }
}

__global__ void k_proj(const float* __restrict__ s,
                       const float* __restrict__ wq,  const float* __restrict__ bq,
                       const float* __restrict__ wkv, const float* __restrict__ bkv,
                       const float* __restrict__ wqp, const float* __restrict__ bqp,
                       const float* __restrict__ wkvp,const float* __restrict__ bkvp) {
    int bx = blockIdx.x;
    const float* W; const float* b; float* out; int Nc; int ct;
    if (bx < 3)       { W = wq;   b = bq;   out = g_qlin;   Nc = HC;       ct = bx; }
    else if (bx < 9)  { W = wkv;  b = bkv;  out = g_kvlin;  Nc = KV_COLS;  ct = bx - 3; }
    else if (bx < 12) { W = wqp;  b = bqp;  out = g_qplin;  Nc = QP_COLS;  ct = bx - 9; }
    else              { W = wkvp; b = bkvp; out = g_kvplin; Nc = KVP_COLS; ct = bx - 12; }
    gemm_tile(s, W, b, out, CN, Nc, blockIdx.y * 32, ct * 64);
}

__global__ void k_outgemm(const float* __restrict__ W, const float* __restrict__ bias,
                          float* __restrict__ out) {
    gemm_tile(g_cat, W, bias, out, CAT_DIM, CN, blockIdx.y * 32, blockIdx.x * 64);
}

// ---------------- point construction ----------------
__global__ void k_points_all(const float* __restrict__ rot, const float* __restrict__ trans) {
    int idx = blockIdx.x * 256 + threadIdx.x;
    if (idx >= N * 192) return;
    int i = idx / 192, p = idx % 192;
    float l0, l1, l2;
    if (p < 48) {
        const float* lin = g_qplin + i * QP_COLS;
        l0 = lin[p]; l1 = lin[48 + p]; l2 = lin[96 + p];
    } else {
        const float* lin = g_kvplin + i * KVP_COLS;
        int pp = p - 48;
        l0 = lin[pp]; l1 = lin[144 + pp]; l2 = lin[288 + pp];
    }
    const float* R = rot + i * 9;
    float o[3];
    #pragma unroll
    for (int d = 0; d < 3; d++)
        o[d] = R[d * 3 + 0] * l0 + R[d * 3 + 1] * l1 + R[d * 3 + 2] * l2 + trans[i * 3 + d];
    if (p < 48) {
        int h = p / PQ, tt = p % PQ;
        #pragma unroll
        for (int d = 0; d < 3; d++) g_qpts[i * 144 + h * 12 + tt * 3 + d] = o[d];
    } else {
        int pp = p - 48;
        int h = pp / 12, tt = pp % 12;
        if (tt < PQ) {
            #pragma unroll
            for (int d = 0; d < 3; d++) g_kpts[i * 144 + h * 12 + tt * 3 + d] = o[d];
        } else {
            #pragma unroll
            for (int d = 0; d < 3; d++) g_vpts[i * 288 + h * 24 + (tt - PQ) * 3 + d] = o[d];
        }
    }
}

// ---------------- qk + pt_att + mask terms (pure WRITE into g_logits) ----------------
__global__ void k_qk(const float* __restrict__ mask, const float* __restrict__ hwts) {
    __shared__ float qs[32][17], ks[32][17];
    __shared__ float qps[32][13], kps[32][13];
    int h = blockIdx.z;
    int i0 = blockIdx.y * 32, j0 = blockIdx.x * 32;
    int tx = threadIdx.x, ty = threadIdx.y;
    int tid = ty * 16 + tx;
    for (int r = 0; r < 2; r++) {
        int idx = tid + 256 * r;
        int ii = idx >> 4, c = idx & 15;
        qs[ii][c] = g_qlin[(i0 + ii) * HC + h * 16 + c];
        ks[ii][c] = g_kvlin[(j0 + ii) * KV_COLS + h * 32 + c];
        if (idx < 384) {
            int i2 = idx / 12, d = idx % 12;
            qps[i2][d] = g_qpts[(i0 + i2) * 144 + h * 12 + d];
            kps[i2][d] = g_kpts[(j0 + i2) * 144 + h * 12 + d];
        }
    }
    __syncthreads();
    float w = hwts[h];
    float hw = logf(1.0f + expf(w)) * 0.13608276348795434f; // softplus * sqrt(1/54)
    const float QK_SCALE = 0.14433756729740643f;            // sqrt(1/48)
    float dot[2][2] = {};
    float pt[2][2] = {};
    #pragma unroll
    for (int c = 0; c < 16; c++) {
        float a0 = qs[ty * 2][c], a1 = qs[ty * 2 + 1][c];
        float b0 = ks[tx * 2][c], b1 = ks[tx * 2 + 1][c];
        dot[0][0] += a0 * b0; dot[0][1] += a0 * b1;
        dot[1][0] += a1 * b0; dot[1][1] += a1 * b1;
    }
    #pragma unroll
    for (int d = 0; d < 12; d++) {
        float a0 = qps[ty * 2][d], a1 = qps[ty * 2 + 1][d];
        float b0 = kps[tx * 2][d], b1 = kps[tx * 2 + 1][d];
        float d00 = a0 - b0, d01 = a0 - b1, d10 = a1 - b0, d11 = a1 - b1;
        pt[0][0] += d00 * d00; pt[0][1] += d01 * d01;
        pt[1][0] += d10 * d10; pt[1][1] += d11 * d11;
    }
    #pragma unroll
    for (int a = 0; a < 2; a++) {
        int i = i0 + ty * 2 + a;
        #pragma unroll
        for (int b = 0; b < 2; b++) {
            int j = j0 + tx * 2 + b;
            float m = mask[i * N + j];
            g_logits[(long)h * NN + i * N + j] =
                QK_SCALE * dot[a][b] - 0.5f * hw * pt[a][b] + INFV * (m - 1.0f);
        }
    }
}

// ---------------- fused z kernel: R13 proven (cp.async double-buffered) ----------------
__global__ void __launch_bounds__(256, 2) k_zfused(const float* __restrict__ z,
                                                   const float* __restrict__ wb,
                                                   const float* __restrict__ bb) {
    extern __shared__ float sm[];
    float* wbT    = sm + ZOFF_WBT;    // [12][128], pre-scaled by sqrt(1/3)
    float* e_sh   = sm + ZOFF_ESH;    // [64][12]
    float* rbias  = sm + ZOFF_RBIAS;  // [4][12][64]
    float* s_S    = sm + ZOFF_S;      // [12]
    float* s_bsbb = sm + ZOFF_BB;

    int i = blockIdx.x;
    int t = threadIdx.x;
    const float BS = 0.57735026918962576f; // sqrt(1/3)
    unsigned int sbase = (unsigned int)__cvta_generic_to_shared(sm);

    for (int idx = t; idx < 12 * 128; idx += 256) {
        int h = idx >> 7, c = idx & 127;
        wbT[idx] = BS * wb[c * 12 + h];
    }
    if (t < 12) {
        s_bsbb[t] = BS * bb[t];
        s_S[t] = 0.0f;
    }

    int rg = t & 63, cq = t >> 6;     // bias mapping
    int c2 = t & 63, g = t >> 6;      // o_pair mapping

    int pf_row[8], pf_c4[8];
    #pragma unroll
    for (int r = 0; r < 8; r++) {
        int idx = t + 256 * r;
        pf_row[r] = idx >> 5;
        pf_c4[r]  = idx & 31;
    }
    int qh = t >> 4, qq4 = t & 15;

    // prologue: prefetch tile 0 into buf0
    #pragma unroll
    for (int r = 0; r < 8; r++) {
        cp16(sbase + (ZOFF_SZ0 + pf_row[r] * 132 + pf_c4[r] * 4) * 4,
             &z[((long)i * N + 0 * 64 + pf_row[r]) * CZ + pf_c4[r] * 4]);
    }
    if (t < 192)
        cp16(sbase + (ZOFF_QKT0 + qh * 64 + qq4 * 4) * 4,
             &g_logits[(long)qh * NN + i * N + 0 * 64 + qq4 * 4]);
    CP_COMMIT();

    unsigned long long acc[12];
    #pragma unroll
    for (int h = 0; h < 12; h++) acc[h] = 0ull;

    for (int tile = 0; tile < 12; tile++) {
        int cur = tile & 1;
        float* s_z = sm + (cur ? ZOFF_SZ1 : ZOFF_SZ0);
        float* qkt = sm + (cur ? ZOFF_QKT1 : ZOFF_QKT0);

        __syncthreads();   // buffers released; init visible (tile 0)

        if (tile < 11) {
            int nxt = (tile + 1) & 1;
            unsigned int zoff = nxt ? ZOFF_SZ1 : ZOFF_SZ0;
            unsigned int qoff = nxt ? ZOFF_QKT1 : ZOFF_QKT0;
            #pragma unroll
            for (int r = 0; r < 8; r++) {
                cp16(sbase + (zoff + pf_row[r] * 132 + pf_c4[r] * 4) * 4,
                     &z[((long)i * N + (tile + 1) * 64 + pf_row[r]) * CZ + pf_c4[r] * 4]);
            }
            if (t < 192)
                cp16(sbase + (qoff + qh * 64 + qq4 * 4) * 4,
                     &g_logits[(long)qh * NN + i * N + (tile + 1) * 64 + qq4 * 4]);
        }
        CP_COMMIT();
        CP_WAIT1();
        __syncthreads();

        // bias partial dot over this thread's column quarter, all 12 heads
        {
            unsigned long long bacc[12];
            #pragma unroll
            for (int h = 0; h < 12; h++) bacc[h] = 0ull;
            const float* zr = &s_z[rg * 132 + cq * 32];
            #pragma unroll
            for (int c4 = 0; c4 < 8; c4++) {
                ulonglong2 zz = *reinterpret_cast<const ulonglong2*>(&zr[c4 * 4]);
                #pragma unroll
                for (int h = 0; h < 12; h++) {
                    ulonglong2 ww = *reinterpret_cast<const ulonglong2*>(&wbT[h * 128 + cq * 32 + c4 * 4]);
                    fma2(bacc[h], zz.x, ww.x);
                    fma2(bacc[h], zz.y, ww.y);
                }
            }
            #pragma unroll
            for (int h = 0; h < 12; h++)
                rbias[cq * 768 + h * 64 + rg] = hsum2(bacc[h]);
        }
        __syncthreads();

        // logits + exp + row-sum partials
        #pragma unroll
        for (int k = 0; k < 3; k++) {
            int h2 = (t >> 6) + 4 * k;
            int r2 = t & 63;
            float l = rbias[0 * 768 + h2 * 64 + r2]
                    + rbias[1 * 768 + h2 * 64 + r2]
                    + rbias[2 * 768 + h2 * 64 + r2]
                    + rbias[3 * 768 + h2 * 64 + r2]
                    + s_bsbb[h2] + qkt[h2 * 64 + r2];
            float e = __expf(l);
            e_sh[r2 * 12 + h2] = e;
            g_logits[(long)h2 * NN + i * N + tile * 64 + r2] = e;
            float ss = e;
            #pragma unroll
            for (int off = 16; off; off >>= 1)
                ss += __shfl_xor_sync(0xffffffffu, ss, off);
            if ((t & 31) == 0) atomicAdd(&s_S[h2], ss);
        }
        __syncthreads();

        // o_pair accumulate from smem tile
        #pragma unroll
        for (int jj = 0; jj < 16; jj++) {
            int j = jj * 4 + g;
            unsigned long long zz = *reinterpret_cast<const unsigned long long*>(&s_z[j * 132 + c2 * 2]);
            const float4* ep = reinterpret_cast<const float4*>(&e_sh[j * 12]);
            float4 e0 = ep[0], e1 = ep[1], e2 = ep[2];
            fma2(acc[0],  zz, pk2(e0.x, e0.x));
            fma2(acc[1],  zz, pk2(e0.y, e0.y));
            fma2(acc[2],  zz, pk2(e0.z, e0.z));
            fma2(acc[3],  zz, pk2(e0.w, e0.w));
            fma2(acc[4],  zz, pk2(e1.x, e1.x));
            fma2(acc[5],  zz, pk2(e1.y, e1.y));
            fma2(acc[6],  zz, pk2(e1.z, e1.z));
            fma2(acc[7],  zz, pk2(e1.w, e1.w));
            fma2(acc[8],  zz, pk2(e2.x, e2.x));
            fma2(acc[9],  zz, pk2(e2.y, e2.y));
            fma2(acc[10], zz, pk2(e2.z, e2.z));
            fma2(acc[11], zz, pk2(e2.w, e2.w));
        }
    }

    // epilogue
    __syncthreads();
    unsigned long long* rbuf = reinterpret_cast<unsigned long long*>(sm + ZOFF_SZ0);
    #pragma unroll
    for (int h = 0; h < 12; h++)
        rbuf[g * 768 + h * 64 + c2] = acc[h];
    __syncthreads();
    #pragma unroll
    for (int r = 0; r < 3; r++) {
        int idx = t + 256 * r;
        int h = idx >> 6, cc = idx & 63;
        float sx = 0.f, sy = 0.f;
        #pragma unroll
        for (int gg = 0; gg < 4; gg++) {
            float x, y;
            unpk2(rbuf[gg * 768 + h * 64 + cc], x, y);
            sx += x; sy += y;
        }
        float inv = 1.0f / s_S[h];
        *reinterpret_cast<float2*>(&g_cat[(long)i * CAT_DIM + 576 + h * 128 + cc * 2]) =
            make_float2(sx * inv, sy * inv);
    }
    if (t < 12)
        g_sinv[t * N + i] = 1.0f / s_S[t];
}

// ---------------- o = a@v, o_pt (+ fused inverse-frame + norm) ----------------
__global__ void k_av(const float* __restrict__ rot, const float* __restrict__ trans) {
    __shared__ float a_sh[32][64];
    __shared__ float vv_sh[64][41];
    __shared__ float pt_sh[32][25];
    int h = blockIdx.y;
    int i0 = blockIdx.x * 32;
    int tid = threadIdx.x;
    int i_local = tid >> 3;
    int cbase = tid & 7;
    float acc[5] = {};
    for (int j0 = 0; j0 < N; j0 += 64) {
        #pragma unroll
        for (int r = 0; r < 8; r++) {
            int idx = tid + 256 * r;
            int ii = idx >> 6, jj = idx & 63;
            a_sh[ii][jj] = g_logits[(long)h * NN + (i0 + ii) * N + j0 + jj];
        }
        #pragma unroll
        for (int r = 0; r < 10; r++) {
            int idx = tid + 256 * r;
            int jj = idx / 40, col = idx % 40;
            float val;
            if (col < 16) val = g_kvlin[(j0 + jj) * KV_COLS + h * 32 + 16 + col];
            else          val = g_vpts[(j0 + jj) * 288 + h * 24 + (col - 16)];
            vv_sh[jj][col] = val;
        }
        __syncthreads();
        #pragma unroll 4
        for (int jj = 0; jj < 64; jj++) {
            float av = a_sh[i_local][jj];
            #pragma unroll
            for (int k = 0; k < 5; k++) acc[k] += av * vv_sh[jj][cbase + 8 * k];
        }
        __syncthreads();
    }
    int i = i0 + i_local;
    float inv = g_sinv[h * N + i];
    #pragma unroll
    for (int k = 0; k < 5; k++) {
        acc[k] *= inv;
        int col = cbase + 8 * k;
        if (col < 16) g_cat[(long)i * CAT_DIM + h * 16 + col] = acc[k];
        else          pt_sh[i_local][col - 16] = acc[k];
    }
    __syncthreads();
    // fused ptfinish: thread = (i_local = tid>>3, pv = tid&7)
    {
        int il = tid >> 3, pv = tid & 7;
        int i2 = i0 + il;
        int hp = h * PV + pv;
        float gx = pt_sh[il][pv * 3 + 0] - trans[i2 * 3 + 0];
        float gy = pt_sh[il][pv * 3 + 1] - trans[i2 * 3 + 1];
        float gz = pt_sh[il][pv * 3 + 2] - trans[i2 * 3 + 2];
        const float* R = rot + i2 * 9;
        float n2 = EPSV;
        #pragma unroll
        for (int jd = 0; jd < 3; jd++) {
            float loc = R[0 * 3 + jd] * gx + R[1 * 3 + jd] * gy + R[2 * 3 + jd] * gz;
            g_cat[(long)i2 * CAT_DIM + 192 + 96 * jd + hp] = loc;
            n2 += loc * loc;
        }
        g_cat[(long)i2 * CAT_DIM + 480 + hp] = sqrtf(n2);
    }
}

// ---------------- launch ----------------
extern "C" void kernel_launch(void* const* d_in, const int* in_sizes, int n_in,
                              void* d_out, int out_size) {
    const float* s     = (const float*)d_in[0];
    const float* z     = (const float*)d_in[1];
    const float* rot   = (const float*)d_in[2];
    const float* trans = (const float*)d_in[3];
    const float* mask  = (const float*)d_in[4];
    const float* wq    = (const float*)d_in[5];
    const float* bq    = (const float*)d_in[6];
    const float* wkv   = (const float*)d_in[7];
    const float* bkv   = (const float*)d_in[8];
    const float* wqp   = (const float*)d_in[9];
    const float* bqp   = (const float*)d_in[10];
    const float* wkvp  = (const float*)d_in[11];
    const float* bkvp  = (const float*)d_in[12];
    const float* wb    = (const float*)d_in[13];
    const float* bb    = (const float*)d_in[14];
    const float* hwts  = (const float*)d_in[15];
    const float* wout  = (const float*)d_in[16];
    const float* bout  = (const float*)d_in[17];
    float* out = (float*)d_out;

    cudaFuncSetAttribute(k_zfused, cudaFuncAttributeMaxDynamicSharedMemorySize, ZF_SMEM_BYTES);

    // projections + points
    k_proj<<<dim3(19, 24), 256>>>(s, wq, bq, wkv, bkv, wqp, bqp, wkvp, bkvp);
    k_points_all<<<(N * 192 + 255) / 256, 256>>>(rot, trans);
    // qk + pt + mask terms -> g_logits (pure write)
    k_qk<<<dim3(N / 32, N / 32, H), dim3(16, 16)>>>(mask, hwts);
    // fused: bias + logits + exp + o_pair; SINGLE z DRAM pass, cp.async pipelined
    k_zfused<<<N, 256, ZF_SMEM_BYTES>>>(z, wb, bb);
    // a @ [v, v_pts] + fused inverse-frame/norm
    k_av<<<dim3(N / 32, H), 256>>>(rot, trans);
    // output projection
    k_outgemm<<<dim3(6, 24), 256>>>(wout, bout, out);
}